// round 6
// baseline (speedup 1.0000x reference)
#include <cuda_runtime.h>
#include <cstdint>
#include <math.h>

// Problem constants
#define Bn   8
#define Ln   1024
#define Vn   1024
#define Dn   2048
#define DVn  1024
#define KTOP 512
#define CAND_CAP 4096
#define HD   1024      // D/2
#define XD   4096      // 2*D
#define OUTL 1536      // L + K = V + K
#define KC   248       // Eigen multithreaded kc (l1=16KB default, mr=12, nr=4)

// ---------------- static device scratch (no allocations allowed) ----------------
__device__ float g_visproj[Bn * Vn * Dn];                 // 67 MB
__device__ float g_lhat[Bn * Ln * Dn];                    // normalized lang
__device__ float g_vhat[Bn * Vn * Dn];                    // normalized visproj
__device__ unsigned long long g_ckey[Bn * CAND_CAP];      // sort keys
__device__ int g_cnt[Bn];
__device__ int g_vl[Bn * KTOP];
__device__ int g_vv[Bn * KTOP];
__device__ int g_n[Bn];
__device__ int g_nkl[Bn];
__device__ int g_rml[Bn * OUTL];
__device__ int g_rmv[Bn * OUTL];
__device__ float g_x[Bn * KTOP * XD];                     // 64 MB
__device__ float g_h[Bn * KTOP * HD];                     // 16 MB

// ---------------- chunked SGEMM tile: C[128x128] = A[128xK] * B[128xK]^T ----------------
// Per-element rounding emulates Eigen ThreadPool contraction on NEON:
//   result = ((c0 + c1) + c2) + ...   (FADD at chunk joins)
//   c_i    = sequential FMA chain over k in [i*KC, min((i+1)*KC, K)), ascending.
__device__ __forceinline__ void sgemm_128(const float* __restrict__ A,
                                          const float* __restrict__ B,
                                          int K, float tot[8][8]) {
    __shared__ float sA[8 * 128];
    __shared__ float sB[8 * 128];
    const int tid  = threadIdx.x;
    const int lrow = tid >> 1;           // 0..127
    const int lk   = (tid & 1) << 2;     // 0 or 4
    const int tx   = (tid & 15) << 3;    // col offset in tile
    const int ty   = (tid >> 4) << 3;    // row offset in tile

    const float* Ap = A + (long)lrow * K + lk;
    const float* Bp = B + (long)lrow * K + lk;

    float cur[8][8];
    #pragma unroll
    for (int i = 0; i < 8; i++)
        #pragma unroll
        for (int j = 0; j < 8; j++) cur[i][j] = 0.f;

    for (int kt = 0; kt < K; kt += 8) {
        float4 av = *(const float4*)(Ap + kt);
        float4 bv = *(const float4*)(Bp + kt);
        __syncthreads();
        sA[(lk + 0) * 128 + lrow] = av.x;
        sA[(lk + 1) * 128 + lrow] = av.y;
        sA[(lk + 2) * 128 + lrow] = av.z;
        sA[(lk + 3) * 128 + lrow] = av.w;
        sB[(lk + 0) * 128 + lrow] = bv.x;
        sB[(lk + 1) * 128 + lrow] = bv.y;
        sB[(lk + 2) * 128 + lrow] = bv.z;
        sB[(lk + 3) * 128 + lrow] = bv.w;
        __syncthreads();
        #pragma unroll
        for (int k = 0; k < 8; k++) {
            float a[8], b[8];
            *(float4*)(a)     = *(const float4*)(sA + k * 128 + ty);
            *(float4*)(a + 4) = *(const float4*)(sA + k * 128 + ty + 4);
            *(float4*)(b)     = *(const float4*)(sB + k * 128 + tx);
            *(float4*)(b + 4) = *(const float4*)(sB + k * 128 + tx + 4);
            #pragma unroll
            for (int i = 0; i < 8; i++)
                #pragma unroll
                for (int j = 0; j < 8; j++)
                    cur[i][j] = __fmaf_rn(a[i], b[j], cur[i][j]);
        }
        int kend = kt + 8;
        if ((kend % KC) == 0 || kend == K) {   // chunk boundary: fold into total
            #pragma unroll
            for (int i = 0; i < 8; i++)
                #pragma unroll
                for (int j = 0; j < 8; j++) {
                    tot[i][j] = __fadd_rn(tot[i][j], cur[i][j]);
                    cur[i][j] = 0.f;
                }
        }
    }
}

// ---------------- kernels ----------------
__global__ void reset_counters() {
    if (threadIdx.x < Bn) g_cnt[threadIdx.x] = 0;
}

// vis_proj[b,v,e] = vision[b,v,:] . W_v2l[e,:] + b_v2l[e]   (b_v2l == 0, FADD harmless)
__global__ __launch_bounds__(256) void gemm_visproj(const float* __restrict__ vision,
                                                    const float* __restrict__ Wv2l,
                                                    const float* __restrict__ bv2l) {
    int b = blockIdx.z;
    const float* A = vision + (long)b * Vn * DVn + (long)blockIdx.y * 128 * DVn;
    const float* B = Wv2l + (long)blockIdx.x * 128 * DVn;
    float acc[8][8] = {};
    sgemm_128(A, B, DVn, acc);
    int tx = (threadIdx.x & 15) << 3;
    int ty = (threadIdx.x >> 4) << 3;
    int m0 = blockIdx.y * 128 + ty;
    int n0 = blockIdx.x * 128 + tx;
    float* C = g_visproj + (long)b * Vn * Dn;
    #pragma unroll
    for (int i = 0; i < 8; i++)
        #pragma unroll
        for (int j = 0; j < 8; j++)
            C[(long)(m0 + i) * Dn + n0 + j] = __fadd_rn(acc[i][j], bv2l[n0 + j]);
}

// normalize rows: fp64 sum of squares (exact), rounded to fp32 norm once;
// elementwise correctly-rounded division (matches XLA divide).
__global__ void normalize_rows(const float* __restrict__ src, float* __restrict__ dst) {
    long row = blockIdx.x;
    const float* p = src + row * Dn;
    double s = 0.0;
    for (int i = threadIdx.x; i < Dn; i += 256) { double v = (double)p[i]; s += v * v; }
    __shared__ double red[256];
    red[threadIdx.x] = s; __syncthreads();
    for (int off = 128; off > 0; off >>= 1) {
        if (threadIdx.x < off) red[threadIdx.x] += red[threadIdx.x + off];
        __syncthreads();
    }
    float norm = fmaxf((float)sqrt(red[0]), 1e-12f);
    float* d = dst + row * Dn;
    for (int i = threadIdx.x; i < Dn; i += 256)
        d[i] = __fdiv_rn(p[i], norm);
}

// sim[b,l,v] = (lhat . vhat) * 10.0f ; collect candidates with v > 0.7f
__global__ __launch_bounds__(256) void gemm_sim(float* __restrict__ simout) {
    int b = blockIdx.z;
    const float* A = g_lhat + ((long)b * Ln + (long)blockIdx.y * 128) * Dn;
    const float* B = g_vhat + ((long)b * Vn + (long)blockIdx.x * 128) * Dn;
    float acc[8][8] = {};
    sgemm_128(A, B, Dn, acc);
    int tx = (threadIdx.x & 15) << 3;
    int ty = (threadIdx.x >> 4) << 3;
    int m0 = blockIdx.y * 128 + ty;
    int n0 = blockIdx.x * 128 + tx;
    float* C = simout + (long)b * Ln * Vn;
    #pragma unroll
    for (int i = 0; i < 8; i++) {
        #pragma unroll
        for (int j = 0; j < 8; j++) {
            float v = __fmul_rn(acc[i][j], 10.0f);   // XLA: x/0.1 -> x * (1/0.1f) = x*10.0f
            C[(long)(m0 + i) * Vn + n0 + j] = v;
            if (v > 0.7f) {
                int p = atomicAdd(&g_cnt[b], 1);
                if (p < CAND_CAP) {
                    unsigned idx = (unsigned)(m0 + i) * Vn + (unsigned)(n0 + j);
                    g_ckey[b * CAND_CAP + p] =
                        ((unsigned long long)__float_as_uint(v) << 20) |
                        (unsigned)(~idx & 0xFFFFFu);
                }
            }
        }
    }
}

// pad unused slots with 0 keys
__global__ void pad_keys() {
    int b = blockIdx.x;
    int cnt = min(g_cnt[b], CAND_CAP);
    for (int i = cnt + threadIdx.x; i < CAND_CAP; i += 256)
        g_ckey[b * CAND_CAP + i] = 0ULL;
}

// per-batch bitonic sort of keys, descending (value desc, index asc on ties)
__global__ __launch_bounds__(1024) void sort_cand() {
    int b = blockIdx.x, t = threadIdx.x;
    __shared__ unsigned long long s[CAND_CAP];
    for (int i = t; i < CAND_CAP; i += 1024)
        s[i] = g_ckey[b * CAND_CAP + i];
    __syncthreads();
    for (int k = 2; k <= CAND_CAP; k <<= 1) {
        for (int j = k >> 1; j > 0; j >>= 1) {
            for (int i = t; i < CAND_CAP; i += 1024) {
                int ixj = i ^ j;
                if (ixj > i) {
                    bool up = ((i & k) == 0);
                    unsigned long long a = s[i], c = s[ixj];
                    if ((a < c) == up) { s[i] = c; s[ixj] = a; }
                }
            }
            __syncthreads();
        }
    }
    for (int i = t; i < CAND_CAP; i += 1024) g_ckey[b * CAND_CAP + i] = s[i];
}

__global__ void select_pairs() {
    int b = blockIdx.x, t = threadIdx.x;
    int cnt = min(g_cnt[b], CAND_CAP);
    int n = min(cnt, KTOP);
    if (t == 0) g_n[b] = n;
    if (t < n) {
        unsigned long long k = g_ckey[b * CAND_CAP + t];
        unsigned idx = (unsigned)(~k) & 0xFFFFFu;
        g_vl[b * KTOP + t] = idx >> 10;
        g_vv[b * KTOP + t] = idx & 1023;
    }
}

// build output row maps: >=0 copy source, -2 merged (written by combine), -1 zero pad
__global__ __launch_bounds__(1024) void build_rowmap() {
    int b = blockIdx.x, t = threadIdx.x;
    __shared__ int flag[1024];
    __shared__ int scan[1024];
    int n = g_n[b];

    // --- language ---
    flag[t] = 0; __syncthreads();
    if (t < n) flag[g_vl[b * KTOP + t]] = 1;
    __syncthreads();
    int keep = 1 - flag[t];
    scan[t] = keep; __syncthreads();
    for (int off = 1; off < 1024; off <<= 1) {
        int v = (t >= off) ? scan[t - off] : 0;
        __syncthreads();
        scan[t] += v;
        __syncthreads();
    }
    int total = scan[1023];
    if (t == 0) g_nkl[b] = total;
    if (keep) g_rml[b * OUTL + scan[t] - 1] = t;
    for (int r = t; r < OUTL; r += 1024)
        if (r >= total) g_rml[b * OUTL + r] = (r < total + n) ? -2 : -1;
    __syncthreads();

    // --- vision ---
    flag[t] = 0; __syncthreads();
    if (t < n) flag[g_vv[b * KTOP + t]] = 1;
    __syncthreads();
    keep = 1 - flag[t];
    scan[t] = keep; __syncthreads();
    for (int off = 1; off < 1024; off <<= 1) {
        int v = (t >= off) ? scan[t - off] : 0;
        __syncthreads();
        scan[t] += v;
        __syncthreads();
    }
    total = scan[1023];
    if (keep) g_rmv[b * OUTL + scan[t] - 1] = t;
    for (int r = t; r < OUTL; r += 1024)
        if (r >= total) g_rmv[b * OUTL + r] = -1;
    __syncthreads();
    if (t < n) g_rmv[b * OUTL + total + t] = g_vv[b * KTOP + t];
}

__global__ void copy_lang(const float* __restrict__ lang, float* __restrict__ out) {
    int r = blockIdx.x, b = blockIdx.y, t = threadIdx.x;
    int s = g_rml[b * OUTL + r];
    if (s == -2) return;  // merged row, written by combine
    float4* dst = (float4*)(out + ((long)b * OUTL + r) * Dn);
    if (s >= 0) {
        const float4* src = (const float4*)(lang + ((long)b * Ln + s) * Dn);
        for (int i = t; i < Dn / 4; i += 256) dst[i] = src[i];
    } else {
        float4 z = make_float4(0.f, 0.f, 0.f, 0.f);
        for (int i = t; i < Dn / 4; i += 256) dst[i] = z;
    }
}

__global__ void copy_vis(const float* __restrict__ vis, float* __restrict__ out) {
    int r = blockIdx.x, b = blockIdx.y, t = threadIdx.x;
    int s = g_rmv[b * OUTL + r];
    float4* dst = (float4*)(out + ((long)b * OUTL + r) * DVn);
    if (s >= 0) {
        const float4* src = (const float4*)(vis + ((long)b * Vn + s) * DVn);
        for (int i = t; i < DVn / 4; i += 256) dst[i] = src[i];
    } else {
        float4 z = make_float4(0.f, 0.f, 0.f, 0.f);
        for (int i = t; i < DVn / 4; i += 256) dst[i] = z;
    }
}

// x row = concat(lang[b, vl], visproj[b, vv])
__global__ void gather_x(const float* __restrict__ lang) {
    int i = blockIdx.x, b = blockIdx.y, t = threadIdx.x;
    float* x = g_x + ((long)b * KTOP + i) * XD;
    if (i < g_n[b]) {
        const float4* lt = (const float4*)(lang + ((long)b * Ln + g_vl[b * KTOP + i]) * Dn);
        const float4* vt = (const float4*)(g_visproj + ((long)b * Vn + g_vv[b * KTOP + i]) * Dn);
        float4* x0 = (float4*)x;
        float4* x1 = (float4*)(x + Dn);
        for (int d = t; d < Dn / 4; d += 256) { x0[d] = lt[d]; x1[d] = vt[d]; }
    } else {
        float4 z = make_float4(0.f, 0.f, 0.f, 0.f);
        float4* x0 = (float4*)x;
        for (int d = t; d < XD / 4; d += 256) x0[d] = z;
    }
}

// h = relu(x @ W_m1^T + b_m1)
__global__ __launch_bounds__(256) void gemm_mlp(const float* __restrict__ Wm1,
                                                const float* __restrict__ bm1) {
    const float* A = g_x + (long)blockIdx.y * 128 * XD;
    const float* B = Wm1 + (long)blockIdx.x * 128 * XD;
    float acc[8][8] = {};
    sgemm_128(A, B, XD, acc);
    int tx = (threadIdx.x & 15) << 3;
    int ty = (threadIdx.x >> 4) << 3;
    int m0 = blockIdx.y * 128 + ty;
    int n0 = blockIdx.x * 128 + tx;
    #pragma unroll
    for (int i = 0; i < 8; i++)
        #pragma unroll
        for (int j = 0; j < 8; j++)
            g_h[(long)(m0 + i) * HD + n0 + j] = fmaxf(acc[i][j] + bm1[n0 + j], 0.f);
}

// logits = h @ W_m2^T + b_m2 ; softmax ; merged = w0*lt + w1*vt
__global__ void combine(const float* __restrict__ lang, const float* __restrict__ Wm2,
                        const float* __restrict__ bm2, float* __restrict__ out) {
    int i = blockIdx.x, b = blockIdx.y, t = threadIdx.x;
    if (i >= g_n[b]) return;
    const float* h = g_h + ((long)b * KTOP + i) * HD;
    float s0 = 0.f, s1 = 0.f;
    for (int k = t; k < HD; k += 256) {
        float hv = h[k];
        s0 += hv * Wm2[k];
        s1 += hv * Wm2[HD + k];
    }
    __shared__ float r0[256], r1[256];
    r0[t] = s0; r1[t] = s1; __syncthreads();
    for (int off = 128; off > 0; off >>= 1) {
        if (t < off) { r0[t] += r0[t + off]; r1[t] += r1[t + off]; }
        __syncthreads();
    }
    float l0 = r0[0] + bm2[0], l1 = r1[0] + bm2[1];
    float mx = fmaxf(l0, l1);
    float e0 = expf(l0 - mx), e1 = expf(l1 - mx);
    float w0 = __fdiv_rn(e0, e0 + e1), w1 = __fdiv_rn(e1, e0 + e1);
    int row = g_nkl[b] + i;
    float* dst = out + ((long)b * OUTL + row) * Dn;
    const float* lt = lang + ((long)b * Ln + g_vl[b * KTOP + i]) * Dn;
    const float* vt = g_visproj + ((long)b * Vn + g_vv[b * KTOP + i]) * Dn;
    for (int d = t; d < Dn; d += 256) dst[d] = w0 * lt[d] + w1 * vt[d];
}

// ---------------- host launch ----------------
extern "C" void kernel_launch(void* const* d_in, const int* in_sizes, int n_in,
                              void* d_out, int out_size) {
    const float* lang = (const float*)d_in[0];
    const float* vis  = (const float*)d_in[1];
    const float* Wv2l = (const float*)d_in[2];
    const float* bv2l = (const float*)d_in[3];
    const float* Wm1  = (const float*)d_in[4];
    const float* bm1  = (const float*)d_in[5];
    const float* Wm2  = (const float*)d_in[6];
    const float* bm2  = (const float*)d_in[7];

    float* out      = (float*)d_out;
    float* out_lang = out;                                   // [8,1536,2048]
    float* out_vis  = out + (long)Bn * OUTL * Dn;            // [8,1536,1024]
    float* out_sim  = out_vis + (long)Bn * OUTL * DVn;       // [8,1024,1024]

    float* lhat;  cudaGetSymbolAddress((void**)&lhat, g_lhat);
    float* vhat;  cudaGetSymbolAddress((void**)&vhat, g_vhat);
    float* vproj; cudaGetSymbolAddress((void**)&vproj, g_visproj);

    reset_counters<<<1, 32>>>();
    gemm_visproj<<<dim3(Dn / 128, Vn / 128, Bn), 256>>>(vis, Wv2l, bv2l);
    normalize_rows<<<Bn * Ln, 256>>>(lang, lhat);
    normalize_rows<<<Bn * Vn, 256>>>(vproj, vhat);
    gemm_sim<<<dim3(Vn / 128, Ln / 128, Bn), 256>>>(out_sim);
    pad_keys<<<Bn, 256>>>();
    sort_cand<<<Bn, 1024>>>();
    select_pairs<<<Bn, KTOP>>>();
    build_rowmap<<<Bn, 1024>>>();
    copy_lang<<<dim3(OUTL, Bn), 256>>>(lang, out_lang);
    copy_vis<<<dim3(OUTL, Bn), 256>>>(vis, out_vis);
    gather_x<<<dim3(KTOP, Bn), 256>>>(lang);
    gemm_mlp<<<dim3(HD / 128, (Bn * KTOP) / 128, 1), 256>>>(Wm1, bm1);
    combine<<<dim3(KTOP, Bn), 256>>>(lang, Wm2, bm2, out_lang);
}

// round 7
// speedup vs baseline: 1.2076x; 1.2076x over previous
#include <cuda_runtime.h>
#include <cstdint>
#include <math.h>

// Problem constants
#define Bn   8
#define Ln   1024
#define Vn   1024
#define Dn   2048
#define DVn  1024
#define KTOP 512
#define CAND_CAP 4096
#define HD   1024      // D/2
#define XD   4096      // 2*D
#define OUTL 1536      // L + K = V + K
#define KC   248       // Eigen multithreaded kc (frozen rounding boundary)

// ---------------- static device scratch (no allocations allowed) ----------------
__device__ float g_visproj[Bn * Vn * Dn];                 // 67 MB
__device__ float g_lhat[Bn * Ln * Dn];                    // normalized lang
__device__ float g_vhat[Bn * Vn * Dn];                    // normalized visproj
__device__ unsigned long long g_ckey[Bn * CAND_CAP];      // sort keys
__device__ int g_cnt[Bn];
__device__ int g_vl[Bn * KTOP];
__device__ int g_vv[Bn * KTOP];
__device__ int g_n[Bn];
__device__ int g_nkl[Bn];
__device__ int g_rml[Bn * OUTL];
__device__ int g_rmv[Bn * OUTL];
__device__ float g_x[Bn * KTOP * XD];                     // 64 MB
__device__ float g_h[Bn * KTOP * HD];                     // 16 MB

// ---------------- double-buffered chunked SGEMM: C[128x128] = A[128xK] * B[128xK]^T ----
// FROZEN ROUNDING: per-element sequential FMA chain, k ascending, FADD fold at every
// KC boundary and at K end (emulates Eigen ThreadPool kc-blocked contraction).
__device__ __forceinline__ void sgemm_128_ck(const float* __restrict__ A,
                                             const float* __restrict__ B,
                                             int K, float tot[8][8]) {
    __shared__ float sA[2][8 * 128];
    __shared__ float sB[2][8 * 128];
    const int tid  = threadIdx.x;
    const int lrow = tid >> 1;           // 0..127
    const int lk   = (tid & 1) << 2;     // 0 or 4
    const int tx   = (tid & 15) << 3;
    const int ty   = (tid >> 4) << 3;

    const float* Ap = A + (long)lrow * K + lk;
    const float* Bp = B + (long)lrow * K + lk;

    float cur[8][8];
    #pragma unroll
    for (int i = 0; i < 8; i++)
        #pragma unroll
        for (int j = 0; j < 8; j++) cur[i][j] = 0.f;

    float4 av = *(const float4*)(Ap);
    float4 bv = *(const float4*)(Bp);
    sA[0][(lk + 0) * 128 + lrow] = av.x;
    sA[0][(lk + 1) * 128 + lrow] = av.y;
    sA[0][(lk + 2) * 128 + lrow] = av.z;
    sA[0][(lk + 3) * 128 + lrow] = av.w;
    sB[0][(lk + 0) * 128 + lrow] = bv.x;
    sB[0][(lk + 1) * 128 + lrow] = bv.y;
    sB[0][(lk + 2) * 128 + lrow] = bv.z;
    sB[0][(lk + 3) * 128 + lrow] = bv.w;
    __syncthreads();

    int buf = 0;
    for (int kt = 0; kt < K; kt += 8) {
        const bool has_next = (kt + 8) < K;
        if (has_next) {
            av = *(const float4*)(Ap + kt + 8);
            bv = *(const float4*)(Bp + kt + 8);
        }
        #pragma unroll
        for (int k = 0; k < 8; k++) {
            float a[8], b[8];
            *(float4*)(a)     = *(const float4*)(&sA[buf][k * 128 + ty]);
            *(float4*)(a + 4) = *(const float4*)(&sA[buf][k * 128 + ty + 4]);
            *(float4*)(b)     = *(const float4*)(&sB[buf][k * 128 + tx]);
            *(float4*)(b + 4) = *(const float4*)(&sB[buf][k * 128 + tx + 4]);
            #pragma unroll
            for (int i = 0; i < 8; i++)
                #pragma unroll
                for (int j = 0; j < 8; j++)
                    cur[i][j] = __fmaf_rn(a[i], b[j], cur[i][j]);
        }
        const int kend = kt + 8;
        if ((kend % KC) == 0 || kend == K) {   // chunk boundary: fold into total
            #pragma unroll
            for (int i = 0; i < 8; i++)
                #pragma unroll
                for (int j = 0; j < 8; j++) {
                    tot[i][j] = __fadd_rn(tot[i][j], cur[i][j]);
                    cur[i][j] = 0.f;
                }
        }
        if (has_next) {
            buf ^= 1;
            sA[buf][(lk + 0) * 128 + lrow] = av.x;
            sA[buf][(lk + 1) * 128 + lrow] = av.y;
            sA[buf][(lk + 2) * 128 + lrow] = av.z;
            sA[buf][(lk + 3) * 128 + lrow] = av.w;
            sB[buf][(lk + 0) * 128 + lrow] = bv.x;
            sB[buf][(lk + 1) * 128 + lrow] = bv.y;
            sB[buf][(lk + 2) * 128 + lrow] = bv.z;
            sB[buf][(lk + 3) * 128 + lrow] = bv.w;
            __syncthreads();
        }
    }
}

// ---------------- double-buffered plain SGEMM (tolerance-loose path: MLP) ----------------
__device__ __forceinline__ void sgemm_128_plain(const float* __restrict__ A,
                                                const float* __restrict__ B,
                                                int K, float acc[8][8]) {
    __shared__ float sA[2][8 * 128];
    __shared__ float sB[2][8 * 128];
    const int tid  = threadIdx.x;
    const int lrow = tid >> 1;
    const int lk   = (tid & 1) << 2;
    const int tx   = (tid & 15) << 3;
    const int ty   = (tid >> 4) << 3;

    const float* Ap = A + (long)lrow * K + lk;
    const float* Bp = B + (long)lrow * K + lk;

    float4 av = *(const float4*)(Ap);
    float4 bv = *(const float4*)(Bp);
    sA[0][(lk + 0) * 128 + lrow] = av.x;
    sA[0][(lk + 1) * 128 + lrow] = av.y;
    sA[0][(lk + 2) * 128 + lrow] = av.z;
    sA[0][(lk + 3) * 128 + lrow] = av.w;
    sB[0][(lk + 0) * 128 + lrow] = bv.x;
    sB[0][(lk + 1) * 128 + lrow] = bv.y;
    sB[0][(lk + 2) * 128 + lrow] = bv.z;
    sB[0][(lk + 3) * 128 + lrow] = bv.w;
    __syncthreads();

    int buf = 0;
    for (int kt = 0; kt < K; kt += 8) {
        const bool has_next = (kt + 8) < K;
        if (has_next) {
            av = *(const float4*)(Ap + kt + 8);
            bv = *(const float4*)(Bp + kt + 8);
        }
        #pragma unroll
        for (int k = 0; k < 8; k++) {
            float a[8], b[8];
            *(float4*)(a)     = *(const float4*)(&sA[buf][k * 128 + ty]);
            *(float4*)(a + 4) = *(const float4*)(&sA[buf][k * 128 + ty + 4]);
            *(float4*)(b)     = *(const float4*)(&sB[buf][k * 128 + tx]);
            *(float4*)(b + 4) = *(const float4*)(&sB[buf][k * 128 + tx + 4]);
            #pragma unroll
            for (int i = 0; i < 8; i++)
                #pragma unroll
                for (int j = 0; j < 8; j++)
                    acc[i][j] = __fmaf_rn(a[i], b[j], acc[i][j]);
        }
        if (has_next) {
            buf ^= 1;
            sA[buf][(lk + 0) * 128 + lrow] = av.x;
            sA[buf][(lk + 1) * 128 + lrow] = av.y;
            sA[buf][(lk + 2) * 128 + lrow] = av.z;
            sA[buf][(lk + 3) * 128 + lrow] = av.w;
            sB[buf][(lk + 0) * 128 + lrow] = bv.x;
            sB[buf][(lk + 1) * 128 + lrow] = bv.y;
            sB[buf][(lk + 2) * 128 + lrow] = bv.z;
            sB[buf][(lk + 3) * 128 + lrow] = bv.w;
            __syncthreads();
        }
    }
}

// ---------------- kernels ----------------
__global__ void reset_counters() {
    if (threadIdx.x < Bn) g_cnt[threadIdx.x] = 0;
}

// vis_proj[b,v,e] = vision[b,v,:] . W_v2l[e,:] + b_v2l[e]
__global__ __launch_bounds__(256) void gemm_visproj(const float* __restrict__ vision,
                                                    const float* __restrict__ Wv2l,
                                                    const float* __restrict__ bv2l) {
    int b = blockIdx.z;
    const float* A = vision + (long)b * Vn * DVn + (long)blockIdx.y * 128 * DVn;
    const float* B = Wv2l + (long)blockIdx.x * 128 * DVn;
    float acc[8][8] = {};
    sgemm_128_ck(A, B, DVn, acc);
    int tx = (threadIdx.x & 15) << 3;
    int ty = (threadIdx.x >> 4) << 3;
    int m0 = blockIdx.y * 128 + ty;
    int n0 = blockIdx.x * 128 + tx;
    float* C = g_visproj + (long)b * Vn * Dn;
    #pragma unroll
    for (int i = 0; i < 8; i++)
        #pragma unroll
        for (int j = 0; j < 8; j++)
            C[(long)(m0 + i) * Dn + n0 + j] = __fadd_rn(acc[i][j], bv2l[n0 + j]);
}

// normalize rows: fp64 sum of squares (order-free: fp64 noise << fp32 ulp),
// fp32-rounded norm, elementwise correctly-rounded division.
__global__ __launch_bounds__(256) void normalize_rows(const float* __restrict__ src,
                                                      float* __restrict__ dst) {
    long row = blockIdx.x;
    const float4* p4 = (const float4*)(src + row * Dn);
    int t = threadIdx.x;
    float4 a = p4[t];
    float4 b = p4[t + 256];
    double s = (double)a.x * a.x + (double)a.y * a.y + (double)a.z * a.z + (double)a.w * a.w
             + (double)b.x * b.x + (double)b.y * b.y + (double)b.z * b.z + (double)b.w * b.w;
    #pragma unroll
    for (int off = 16; off > 0; off >>= 1)
        s += __shfl_down_sync(0xFFFFFFFFu, s, off);
    __shared__ double ws[8];
    __shared__ float nsh;
    if ((t & 31) == 0) ws[t >> 5] = s;
    __syncthreads();
    if (t == 0) {
        double tot = ((ws[0] + ws[1]) + (ws[2] + ws[3])) + ((ws[4] + ws[5]) + (ws[6] + ws[7]));
        nsh = fmaxf((float)sqrt(tot), 1e-12f);
    }
    __syncthreads();
    float n = nsh;
    float4* d4 = (float4*)(dst + row * Dn);
    a.x = __fdiv_rn(a.x, n); a.y = __fdiv_rn(a.y, n);
    a.z = __fdiv_rn(a.z, n); a.w = __fdiv_rn(a.w, n);
    b.x = __fdiv_rn(b.x, n); b.y = __fdiv_rn(b.y, n);
    b.z = __fdiv_rn(b.z, n); b.w = __fdiv_rn(b.w, n);
    d4[t] = a;
    d4[t + 256] = b;
}

// sim[b,l,v] = (lhat . vhat) * 10.0f ; collect candidates with v > 0.7f
__global__ __launch_bounds__(256) void gemm_sim(float* __restrict__ simout) {
    int b = blockIdx.z;
    const float* A = g_lhat + ((long)b * Ln + (long)blockIdx.y * 128) * Dn;
    const float* B = g_vhat + ((long)b * Vn + (long)blockIdx.x * 128) * Dn;
    float acc[8][8] = {};
    sgemm_128_ck(A, B, Dn, acc);
    int tx = (threadIdx.x & 15) << 3;
    int ty = (threadIdx.x >> 4) << 3;
    int m0 = blockIdx.y * 128 + ty;
    int n0 = blockIdx.x * 128 + tx;
    float* C = simout + (long)b * Ln * Vn;
    #pragma unroll
    for (int i = 0; i < 8; i++) {
        #pragma unroll
        for (int j = 0; j < 8; j++) {
            float v = __fmul_rn(acc[i][j], 10.0f);   // XLA: x/0.1 -> x * 10.0f
            C[(long)(m0 + i) * Vn + n0 + j] = v;
            if (v > 0.7f) {
                int p = atomicAdd(&g_cnt[b], 1);
                if (p < CAND_CAP) {
                    unsigned idx = (unsigned)(m0 + i) * Vn + (unsigned)(n0 + j);
                    g_ckey[b * CAND_CAP + p] =
                        ((unsigned long long)__float_as_uint(v) << 20) |
                        (unsigned)(~idx & 0xFFFFFu);
                }
            }
        }
    }
}

// per-batch bitonic sort of keys, descending (value desc, index asc on ties); pads inline
__global__ __launch_bounds__(1024) void sort_cand() {
    int b = blockIdx.x, t = threadIdx.x;
    __shared__ unsigned long long s[CAND_CAP];
    int cnt = min(g_cnt[b], CAND_CAP);
    for (int i = t; i < CAND_CAP; i += 1024)
        s[i] = (i < cnt) ? g_ckey[b * CAND_CAP + i] : 0ULL;
    __syncthreads();
    for (int k = 2; k <= CAND_CAP; k <<= 1) {
        for (int j = k >> 1; j > 0; j >>= 1) {
            for (int i = t; i < CAND_CAP; i += 1024) {
                int ixj = i ^ j;
                if (ixj > i) {
                    bool up = ((i & k) == 0);
                    unsigned long long a = s[i], c = s[ixj];
                    if ((a < c) == up) { s[i] = c; s[ixj] = a; }
                }
            }
            __syncthreads();
        }
    }
    for (int i = t; i < CAND_CAP; i += 1024) g_ckey[b * CAND_CAP + i] = s[i];
}

__global__ void select_pairs() {
    int b = blockIdx.x, t = threadIdx.x;
    int cnt = min(g_cnt[b], CAND_CAP);
    int n = min(cnt, KTOP);
    if (t == 0) g_n[b] = n;
    if (t < n) {
        unsigned long long k = g_ckey[b * CAND_CAP + t];
        unsigned idx = (unsigned)(~k) & 0xFFFFFu;
        g_vl[b * KTOP + t] = idx >> 10;
        g_vv[b * KTOP + t] = idx & 1023;
    }
}

// build output row maps: >=0 copy source, -2 merged (written by combine), -1 zero pad
__global__ __launch_bounds__(1024) void build_rowmap() {
    int b = blockIdx.x, t = threadIdx.x;
    __shared__ int flag[1024];
    __shared__ int scan[1024];
    int n = g_n[b];

    // --- language ---
    flag[t] = 0; __syncthreads();
    if (t < n) flag[g_vl[b * KTOP + t]] = 1;
    __syncthreads();
    int keep = 1 - flag[t];
    scan[t] = keep; __syncthreads();
    for (int off = 1; off < 1024; off <<= 1) {
        int v = (t >= off) ? scan[t - off] : 0;
        __syncthreads();
        scan[t] += v;
        __syncthreads();
    }
    int total = scan[1023];
    if (t == 0) g_nkl[b] = total;
    if (keep) g_rml[b * OUTL + scan[t] - 1] = t;
    for (int r = t; r < OUTL; r += 1024)
        if (r >= total) g_rml[b * OUTL + r] = (r < total + n) ? -2 : -1;
    __syncthreads();

    // --- vision ---
    flag[t] = 0; __syncthreads();
    if (t < n) flag[g_vv[b * KTOP + t]] = 1;
    __syncthreads();
    keep = 1 - flag[t];
    scan[t] = keep; __syncthreads();
    for (int off = 1; off < 1024; off <<= 1) {
        int v = (t >= off) ? scan[t - off] : 0;
        __syncthreads();
        scan[t] += v;
        __syncthreads();
    }
    total = scan[1023];
    if (keep) g_rmv[b * OUTL + scan[t] - 1] = t;
    for (int r = t; r < OUTL; r += 1024)
        if (r >= total) g_rmv[b * OUTL + r] = -1;
    __syncthreads();
    if (t < n) g_rmv[b * OUTL + total + t] = g_vv[b * KTOP + t];
}

__global__ void copy_lang(const float* __restrict__ lang, float* __restrict__ out) {
    int r = blockIdx.x, b = blockIdx.y, t = threadIdx.x;
    int s = g_rml[b * OUTL + r];
    if (s == -2) return;  // merged row, written by combine
    float4* dst = (float4*)(out + ((long)b * OUTL + r) * Dn);
    if (s >= 0) {
        const float4* src = (const float4*)(lang + ((long)b * Ln + s) * Dn);
        for (int i = t; i < Dn / 4; i += 256) dst[i] = src[i];
    } else {
        float4 z = make_float4(0.f, 0.f, 0.f, 0.f);
        for (int i = t; i < Dn / 4; i += 256) dst[i] = z;
    }
}

__global__ void copy_vis(const float* __restrict__ vis, float* __restrict__ out) {
    int r = blockIdx.x, b = blockIdx.y, t = threadIdx.x;
    int s = g_rmv[b * OUTL + r];
    float4* dst = (float4*)(out + ((long)b * OUTL + r) * DVn);
    if (s >= 0) {
        const float4* src = (const float4*)(vis + ((long)b * Vn + s) * DVn);
        for (int i = t; i < DVn / 4; i += 256) dst[i] = src[i];
    } else {
        float4 z = make_float4(0.f, 0.f, 0.f, 0.f);
        for (int i = t; i < DVn / 4; i += 256) dst[i] = z;
    }
}

// x row = concat(lang[b, vl], visproj[b, vv])
__global__ void gather_x(const float* __restrict__ lang) {
    int i = blockIdx.x, b = blockIdx.y, t = threadIdx.x;
    float* x = g_x + ((long)b * KTOP + i) * XD;
    if (i < g_n[b]) {
        const float4* lt = (const float4*)(lang + ((long)b * Ln + g_vl[b * KTOP + i]) * Dn);
        const float4* vt = (const float4*)(g_visproj + ((long)b * Vn + g_vv[b * KTOP + i]) * Dn);
        float4* x0 = (float4*)x;
        float4* x1 = (float4*)(x + Dn);
        for (int d = t; d < Dn / 4; d += 256) { x0[d] = lt[d]; x1[d] = vt[d]; }
    } else {
        float4 z = make_float4(0.f, 0.f, 0.f, 0.f);
        float4* x0 = (float4*)x;
        for (int d = t; d < XD / 4; d += 256) x0[d] = z;
    }
}

// h = relu(x @ W_m1^T + b_m1)   (tolerance-loose: plain accumulation)
__global__ __launch_bounds__(256) void gemm_mlp(const float* __restrict__ Wm1,
                                                const float* __restrict__ bm1) {
    const float* A = g_x + (long)blockIdx.y * 128 * XD;
    const float* B = Wm1 + (long)blockIdx.x * 128 * XD;
    float acc[8][8] = {};
    sgemm_128_plain(A, B, XD, acc);
    int tx = (threadIdx.x & 15) << 3;
    int ty = (threadIdx.x >> 4) << 3;
    int m0 = blockIdx.y * 128 + ty;
    int n0 = blockIdx.x * 128 + tx;
    #pragma unroll
    for (int i = 0; i < 8; i++)
        #pragma unroll
        for (int j = 0; j < 8; j++)
            g_h[(long)(m0 + i) * HD + n0 + j] = fmaxf(acc[i][j] + bm1[n0 + j], 0.f);
}

// logits = h @ W_m2^T + b_m2 ; softmax ; merged = w0*lt + w1*vt
__global__ void combine(const float* __restrict__ lang, const float* __restrict__ Wm2,
                        const float* __restrict__ bm2, float* __restrict__ out) {
    int i = blockIdx.x, b = blockIdx.y, t = threadIdx.x;
    if (i >= g_n[b]) return;
    const float* h = g_h + ((long)b * KTOP + i) * HD;
    float s0 = 0.f, s1 = 0.f;
    for (int k = t; k < HD; k += 256) {
        float hv = h[k];
        s0 += hv * Wm2[k];
        s1 += hv * Wm2[HD + k];
    }
    __shared__ float r0[256], r1[256];
    r0[t] = s0; r1[t] = s1; __syncthreads();
    for (int off = 128; off > 0; off >>= 1) {
        if (t < off) { r0[t] += r0[t + off]; r1[t] += r1[t + off]; }
        __syncthreads();
    }
    float l0 = r0[0] + bm2[0], l1 = r1[0] + bm2[1];
    float mx = fmaxf(l0, l1);
    float e0 = expf(l0 - mx), e1 = expf(l1 - mx);
    float w0 = __fdiv_rn(e0, e0 + e1), w1 = __fdiv_rn(e1, e0 + e1);
    int row = g_nkl[b] + i;
    float* dst = out + ((long)b * OUTL + row) * Dn;
    const float* lt = lang + ((long)b * Ln + g_vl[b * KTOP + i]) * Dn;
    const float* vt = g_visproj + ((long)b * Vn + g_vv[b * KTOP + i]) * Dn;
    for (int d = t; d < Dn; d += 256) dst[d] = w0 * lt[d] + w1 * vt[d];
}

// ---------------- host launch ----------------
extern "C" void kernel_launch(void* const* d_in, const int* in_sizes, int n_in,
                              void* d_out, int out_size) {
    const float* lang = (const float*)d_in[0];
    const float* vis  = (const float*)d_in[1];
    const float* Wv2l = (const float*)d_in[2];
    const float* bv2l = (const float*)d_in[3];
    const float* Wm1  = (const float*)d_in[4];
    const float* bm1  = (const float*)d_in[5];
    const float* Wm2  = (const float*)d_in[6];
    const float* bm2  = (const float*)d_in[7];

    float* out      = (float*)d_out;
    float* out_lang = out;                                   // [8,1536,2048]
    float* out_vis  = out + (long)Bn * OUTL * Dn;            // [8,1536,1024]
    float* out_sim  = out_vis + (long)Bn * OUTL * DVn;       // [8,1024,1024]

    float* lhat;  cudaGetSymbolAddress((void**)&lhat, g_lhat);
    float* vhat;  cudaGetSymbolAddress((void**)&vhat, g_vhat);
    float* vproj; cudaGetSymbolAddress((void**)&vproj, g_visproj);

    reset_counters<<<1, 32>>>();
    normalize_rows<<<Bn * Ln, 256>>>(lang, lhat);
    gemm_visproj<<<dim3(Dn / 128, Vn / 128, Bn), 256>>>(vis, Wv2l, bv2l);
    normalize_rows<<<Bn * Vn, 256>>>(vproj, vhat);
    gemm_sim<<<dim3(Vn / 128, Ln / 128, Bn), 256>>>(out_sim);
    sort_cand<<<Bn, 1024>>>();
    select_pairs<<<Bn, KTOP>>>();
    build_rowmap<<<Bn, 1024>>>();
    copy_lang<<<dim3(OUTL, Bn), 256>>>(lang, out_lang);
    copy_vis<<<dim3(OUTL, Bn), 256>>>(vis, out_vis);
    gather_x<<<dim3(KTOP, Bn), 256>>>(lang);
    gemm_mlp<<<dim3(HD / 128, (Bn * KTOP) / 128, 1), 256>>>(Wm1, bm1);
    combine<<<dim3(KTOP, Bn), 256>>>(lang, Wm2, bm2, out_lang);
}

// round 8
// speedup vs baseline: 1.2850x; 1.0641x over previous
#include <cuda_runtime.h>
#include <cstdint>
#include <math.h>

// Problem constants
#define Bn   8
#define Ln   1024
#define Vn   1024
#define Dn   2048
#define DVn  1024
#define KTOP 512
#define CAND_CAP 4096
#define HD   1024      // D/2
#define XD   4096      // 2*D
#define OUTL 1536      // L + K = V + K
#define KC   248       // Eigen multithreaded kc (frozen rounding boundary)

// ---------------- static device scratch (no allocations allowed) ----------------
__device__ float g_visproj[Bn * Vn * Dn];                 // 67 MB
__device__ float g_lhat[Bn * Ln * Dn];                    // normalized lang
__device__ float g_vhat[Bn * Vn * Dn];                    // normalized visproj
__device__ unsigned long long g_ckey[Bn * CAND_CAP];      // sort keys
__device__ int g_cnt[Bn];
__device__ int g_vl[Bn * KTOP];
__device__ int g_vv[Bn * KTOP];
__device__ int g_n[Bn];
__device__ int g_nkl[Bn];
__device__ int g_rml[Bn * OUTL];
__device__ int g_rmv[Bn * OUTL];
__device__ float g_x[Bn * KTOP * XD];                     // 64 MB
__device__ float g_h[Bn * KTOP * HD];                     // 16 MB

// ---------------- f32x2 packed helpers (Blackwell FFMA2 path) ----------------
// Each lane of fma.rn.f32x2 is a full IEEE fp32 fma.rn — per-element rounding is
// identical to scalar __fmaf_rn. Pairing is along the j (output) axis only; the
// k-reduction order of every element is unchanged.
__device__ __forceinline__ unsigned long long dup_f32x2(float x) {
    unsigned long long r;
    asm("mov.b64 %0, {%1, %1};" : "=l"(r) : "r"(__float_as_uint(x)));
    return r;
}
__device__ __forceinline__ void fma_f32x2(unsigned long long& d,
                                          unsigned long long a, unsigned long long b) {
    asm("fma.rn.f32x2 %0, %1, %2, %0;" : "+l"(d) : "l"(a), "l"(b));
}
__device__ __forceinline__ void add_f32x2(unsigned long long& d, unsigned long long a) {
    asm("add.rn.f32x2 %0, %0, %1;" : "+l"(d) : "l"(a));
}
__device__ __forceinline__ float2 unpack_f32x2(unsigned long long v) {
    unsigned lo, hi;
    asm("mov.b64 {%0, %1}, %2;" : "=r"(lo), "=r"(hi) : "l"(v));
    return make_float2(__uint_as_float(lo), __uint_as_float(hi));
}

// ---------------- double-buffered chunked SGEMM (f32x2): C[128x128] = A·B^T ----------
// FROZEN ROUNDING per element: sequential FMA chain, k ascending, FADD fold at every
// KC boundary and at K end. tot[i][p] packs outputs (j=2p, j=2p+1).
__device__ __forceinline__ void sgemm_128_ck(const float* __restrict__ A,
                                             const float* __restrict__ B,
                                             int K, unsigned long long tot[8][4]) {
    __shared__ float sA[2][8 * 128];
    __shared__ float sB[2][8 * 128];
    const int tid  = threadIdx.x;
    const int lrow = tid >> 1;           // 0..127
    const int lk   = (tid & 1) << 2;     // 0 or 4
    const int tx   = (tid & 15) << 3;
    const int ty   = (tid >> 4) << 3;

    const float* Ap = A + (long)lrow * K + lk;
    const float* Bp = B + (long)lrow * K + lk;

    unsigned long long cur[8][4];
    #pragma unroll
    for (int i = 0; i < 8; i++)
        #pragma unroll
        for (int p = 0; p < 4; p++) cur[i][p] = 0ULL;

    float4 av = *(const float4*)(Ap);
    float4 bv = *(const float4*)(Bp);
    sA[0][(lk + 0) * 128 + lrow] = av.x;
    sA[0][(lk + 1) * 128 + lrow] = av.y;
    sA[0][(lk + 2) * 128 + lrow] = av.z;
    sA[0][(lk + 3) * 128 + lrow] = av.w;
    sB[0][(lk + 0) * 128 + lrow] = bv.x;
    sB[0][(lk + 1) * 128 + lrow] = bv.y;
    sB[0][(lk + 2) * 128 + lrow] = bv.z;
    sB[0][(lk + 3) * 128 + lrow] = bv.w;
    __syncthreads();

    int buf = 0;
    for (int kt = 0; kt < K; kt += 8) {
        const bool has_next = (kt + 8) < K;
        if (has_next) {
            av = *(const float4*)(Ap + kt + 8);
            bv = *(const float4*)(Bp + kt + 8);
        }
        #pragma unroll
        for (int k = 0; k < 8; k++) {
            float4 a0 = *(const float4*)(&sA[buf][k * 128 + ty]);
            float4 a1 = *(const float4*)(&sA[buf][k * 128 + ty + 4]);
            ulonglong2 bb0 = *(const ulonglong2*)(&sB[buf][k * 128 + tx]);
            ulonglong2 bb1 = *(const ulonglong2*)(&sB[buf][k * 128 + tx + 4]);
            unsigned long long b2[4] = { bb0.x, bb0.y, bb1.x, bb1.y };
            unsigned long long ad[8];
            ad[0] = dup_f32x2(a0.x); ad[1] = dup_f32x2(a0.y);
            ad[2] = dup_f32x2(a0.z); ad[3] = dup_f32x2(a0.w);
            ad[4] = dup_f32x2(a1.x); ad[5] = dup_f32x2(a1.y);
            ad[6] = dup_f32x2(a1.z); ad[7] = dup_f32x2(a1.w);
            #pragma unroll
            for (int i = 0; i < 8; i++)
                #pragma unroll
                for (int p = 0; p < 4; p++)
                    fma_f32x2(cur[i][p], ad[i], b2[p]);
        }
        const int kend = kt + 8;
        if ((kend % KC) == 0 || kend == K) {   // chunk boundary: fold into total
            #pragma unroll
            for (int i = 0; i < 8; i++)
                #pragma unroll
                for (int p = 0; p < 4; p++) {
                    add_f32x2(tot[i][p], cur[i][p]);
                    cur[i][p] = 0ULL;
                }
        }
        if (has_next) {
            buf ^= 1;
            sA[buf][(lk + 0) * 128 + lrow] = av.x;
            sA[buf][(lk + 1) * 128 + lrow] = av.y;
            sA[buf][(lk + 2) * 128 + lrow] = av.z;
            sA[buf][(lk + 3) * 128 + lrow] = av.w;
            sB[buf][(lk + 0) * 128 + lrow] = bv.x;
            sB[buf][(lk + 1) * 128 + lrow] = bv.y;
            sB[buf][(lk + 2) * 128 + lrow] = bv.z;
            sB[buf][(lk + 3) * 128 + lrow] = bv.w;
            __syncthreads();
        }
    }
}

// ---------------- double-buffered plain SGEMM (f32x2, tolerance-loose: MLP) ----------
__device__ __forceinline__ void sgemm_128_plain(const float* __restrict__ A,
                                                const float* __restrict__ B,
                                                int K, unsigned long long tot[8][4]) {
    __shared__ float sA[2][8 * 128];
    __shared__ float sB[2][8 * 128];
    const int tid  = threadIdx.x;
    const int lrow = tid >> 1;
    const int lk   = (tid & 1) << 2;
    const int tx   = (tid & 15) << 3;
    const int ty   = (tid >> 4) << 3;

    const float* Ap = A + (long)lrow * K + lk;
    const float* Bp = B + (long)lrow * K + lk;

    float4 av = *(const float4*)(Ap);
    float4 bv = *(const float4*)(Bp);
    sA[0][(lk + 0) * 128 + lrow] = av.x;
    sA[0][(lk + 1) * 128 + lrow] = av.y;
    sA[0][(lk + 2) * 128 + lrow] = av.z;
    sA[0][(lk + 3) * 128 + lrow] = av.w;
    sB[0][(lk + 0) * 128 + lrow] = bv.x;
    sB[0][(lk + 1) * 128 + lrow] = bv.y;
    sB[0][(lk + 2) * 128 + lrow] = bv.z;
    sB[0][(lk + 3) * 128 + lrow] = bv.w;
    __syncthreads();

    int buf = 0;
    for (int kt = 0; kt < K; kt += 8) {
        const bool has_next = (kt + 8) < K;
        if (has_next) {
            av = *(const float4*)(Ap + kt + 8);
            bv = *(const float4*)(Bp + kt + 8);
        }
        #pragma unroll
        for (int k = 0; k < 8; k++) {
            float4 a0 = *(const float4*)(&sA[buf][k * 128 + ty]);
            float4 a1 = *(const float4*)(&sA[buf][k * 128 + ty + 4]);
            ulonglong2 bb0 = *(const ulonglong2*)(&sB[buf][k * 128 + tx]);
            ulonglong2 bb1 = *(const ulonglong2*)(&sB[buf][k * 128 + tx + 4]);
            unsigned long long b2[4] = { bb0.x, bb0.y, bb1.x, bb1.y };
            unsigned long long ad[8];
            ad[0] = dup_f32x2(a0.x); ad[1] = dup_f32x2(a0.y);
            ad[2] = dup_f32x2(a0.z); ad[3] = dup_f32x2(a0.w);
            ad[4] = dup_f32x2(a1.x); ad[5] = dup_f32x2(a1.y);
            ad[6] = dup_f32x2(a1.z); ad[7] = dup_f32x2(a1.w);
            #pragma unroll
            for (int i = 0; i < 8; i++)
                #pragma unroll
                for (int p = 0; p < 4; p++)
                    fma_f32x2(tot[i][p], ad[i], b2[p]);
        }
        if (has_next) {
            buf ^= 1;
            sA[buf][(lk + 0) * 128 + lrow] = av.x;
            sA[buf][(lk + 1) * 128 + lrow] = av.y;
            sA[buf][(lk + 2) * 128 + lrow] = av.z;
            sA[buf][(lk + 3) * 128 + lrow] = av.w;
            sB[buf][(lk + 0) * 128 + lrow] = bv.x;
            sB[buf][(lk + 1) * 128 + lrow] = bv.y;
            sB[buf][(lk + 2) * 128 + lrow] = bv.z;
            sB[buf][(lk + 3) * 128 + lrow] = bv.w;
            __syncthreads();
        }
    }
}

// ---------------- kernels ----------------
__global__ void reset_counters() {
    if (threadIdx.x < Bn) g_cnt[threadIdx.x] = 0;
}

// vis_proj[b,v,e] = vision[b,v,:] . W_v2l[e,:] + b_v2l[e]
__global__ __launch_bounds__(256) void gemm_visproj(const float* __restrict__ vision,
                                                    const float* __restrict__ Wv2l,
                                                    const float* __restrict__ bv2l) {
    int b = blockIdx.z;
    const float* A = vision + (long)b * Vn * DVn + (long)blockIdx.y * 128 * DVn;
    const float* B = Wv2l + (long)blockIdx.x * 128 * DVn;
    unsigned long long acc[8][4];
    #pragma unroll
    for (int i = 0; i < 8; i++)
        #pragma unroll
        for (int p = 0; p < 4; p++) acc[i][p] = 0ULL;
    sgemm_128_ck(A, B, DVn, acc);
    int tx = (threadIdx.x & 15) << 3;
    int ty = (threadIdx.x >> 4) << 3;
    int m0 = blockIdx.y * 128 + ty;
    int n0 = blockIdx.x * 128 + tx;
    float* C = g_visproj + (long)b * Vn * Dn;
    #pragma unroll
    for (int i = 0; i < 8; i++)
        #pragma unroll
        for (int p = 0; p < 4; p++) {
            float2 v = unpack_f32x2(acc[i][p]);
            int j = n0 + 2 * p;
            C[(long)(m0 + i) * Dn + j]     = __fadd_rn(v.x, bv2l[j]);
            C[(long)(m0 + i) * Dn + j + 1] = __fadd_rn(v.y, bv2l[j + 1]);
        }
}

// normalize rows: fp64 sum of squares (order-free: fp64 noise << fp32 ulp),
// fp32-rounded norm, elementwise correctly-rounded division.
__global__ __launch_bounds__(256) void normalize_rows(const float* __restrict__ src,
                                                      float* __restrict__ dst) {
    long row = blockIdx.x;
    const float4* p4 = (const float4*)(src + row * Dn);
    int t = threadIdx.x;
    float4 a = p4[t];
    float4 b = p4[t + 256];
    double s = (double)a.x * a.x + (double)a.y * a.y + (double)a.z * a.z + (double)a.w * a.w
             + (double)b.x * b.x + (double)b.y * b.y + (double)b.z * b.z + (double)b.w * b.w;
    #pragma unroll
    for (int off = 16; off > 0; off >>= 1)
        s += __shfl_down_sync(0xFFFFFFFFu, s, off);
    __shared__ double ws[8];
    __shared__ float nsh;
    if ((t & 31) == 0) ws[t >> 5] = s;
    __syncthreads();
    if (t == 0) {
        double tot = ((ws[0] + ws[1]) + (ws[2] + ws[3])) + ((ws[4] + ws[5]) + (ws[6] + ws[7]));
        nsh = fmaxf((float)sqrt(tot), 1e-12f);
    }
    __syncthreads();
    float n = nsh;
    float4* d4 = (float4*)(dst + row * Dn);
    a.x = __fdiv_rn(a.x, n); a.y = __fdiv_rn(a.y, n);
    a.z = __fdiv_rn(a.z, n); a.w = __fdiv_rn(a.w, n);
    b.x = __fdiv_rn(b.x, n); b.y = __fdiv_rn(b.y, n);
    b.z = __fdiv_rn(b.z, n); b.w = __fdiv_rn(b.w, n);
    d4[t] = a;
    d4[t + 256] = b;
}

// sim[b,l,v] = (lhat . vhat) * 10.0f ; collect candidates with v > 0.7f
__global__ __launch_bounds__(256) void gemm_sim(float* __restrict__ simout) {
    int b = blockIdx.z;
    const float* A = g_lhat + ((long)b * Ln + (long)blockIdx.y * 128) * Dn;
    const float* B = g_vhat + ((long)b * Vn + (long)blockIdx.x * 128) * Dn;
    unsigned long long acc[8][4];
    #pragma unroll
    for (int i = 0; i < 8; i++)
        #pragma unroll
        for (int p = 0; p < 4; p++) acc[i][p] = 0ULL;
    sgemm_128_ck(A, B, Dn, acc);
    int tx = (threadIdx.x & 15) << 3;
    int ty = (threadIdx.x >> 4) << 3;
    int m0 = blockIdx.y * 128 + ty;
    int n0 = blockIdx.x * 128 + tx;
    float* C = simout + (long)b * Ln * Vn;
    #pragma unroll
    for (int i = 0; i < 8; i++) {
        #pragma unroll
        for (int p = 0; p < 4; p++) {
            float2 vp = unpack_f32x2(acc[i][p]);
            #pragma unroll
            for (int h = 0; h < 2; h++) {
                int j = n0 + 2 * p + h;
                float v = __fmul_rn(h ? vp.y : vp.x, 10.0f);   // XLA: x/0.1 -> x*10.0f
                C[(long)(m0 + i) * Vn + j] = v;
                if (v > 0.7f) {
                    int pos = atomicAdd(&g_cnt[b], 1);
                    if (pos < CAND_CAP) {
                        unsigned idx = (unsigned)(m0 + i) * Vn + (unsigned)j;
                        g_ckey[b * CAND_CAP + pos] =
                            ((unsigned long long)__float_as_uint(v) << 20) |
                            (unsigned)(~idx & 0xFFFFFu);
                    }
                }
            }
        }
    }
}

// per-batch bitonic sort of keys, descending (value desc, index asc on ties); pads inline
__global__ __launch_bounds__(1024) void sort_cand() {
    int b = blockIdx.x, t = threadIdx.x;
    __shared__ unsigned long long s[CAND_CAP];
    int cnt = min(g_cnt[b], CAND_CAP);
    for (int i = t; i < CAND_CAP; i += 1024)
        s[i] = (i < cnt) ? g_ckey[b * CAND_CAP + i] : 0ULL;
    __syncthreads();
    for (int k = 2; k <= CAND_CAP; k <<= 1) {
        for (int j = k >> 1; j > 0; j >>= 1) {
            for (int i = t; i < CAND_CAP; i += 1024) {
                int ixj = i ^ j;
                if (ixj > i) {
                    bool up = ((i & k) == 0);
                    unsigned long long a = s[i], c = s[ixj];
                    if ((a < c) == up) { s[i] = c; s[ixj] = a; }
                }
            }
            __syncthreads();
        }
    }
    for (int i = t; i < CAND_CAP; i += 1024) g_ckey[b * CAND_CAP + i] = s[i];
}

__global__ void select_pairs() {
    int b = blockIdx.x, t = threadIdx.x;
    int cnt = min(g_cnt[b], CAND_CAP);
    int n = min(cnt, KTOP);
    if (t == 0) g_n[b] = n;
    if (t < n) {
        unsigned long long k = g_ckey[b * CAND_CAP + t];
        unsigned idx = (unsigned)(~k) & 0xFFFFFu;
        g_vl[b * KTOP + t] = idx >> 10;
        g_vv[b * KTOP + t] = idx & 1023;
    }
}

// build output row maps: >=0 copy source, -2 merged (written by combine), -1 zero pad
__global__ __launch_bounds__(1024) void build_rowmap() {
    int b = blockIdx.x, t = threadIdx.x;
    __shared__ int flag[1024];
    __shared__ int scan[1024];
    int n = g_n[b];

    // --- language ---
    flag[t] = 0; __syncthreads();
    if (t < n) flag[g_vl[b * KTOP + t]] = 1;
    __syncthreads();
    int keep = 1 - flag[t];
    scan[t] = keep; __syncthreads();
    for (int off = 1; off < 1024; off <<= 1) {
        int v = (t >= off) ? scan[t - off] : 0;
        __syncthreads();
        scan[t] += v;
        __syncthreads();
    }
    int total = scan[1023];
    if (t == 0) g_nkl[b] = total;
    if (keep) g_rml[b * OUTL + scan[t] - 1] = t;
    for (int r = t; r < OUTL; r += 1024)
        if (r >= total) g_rml[b * OUTL + r] = (r < total + n) ? -2 : -1;
    __syncthreads();

    // --- vision ---
    flag[t] = 0; __syncthreads();
    if (t < n) flag[g_vv[b * KTOP + t]] = 1;
    __syncthreads();
    keep = 1 - flag[t];
    scan[t] = keep; __syncthreads();
    for (int off = 1; off < 1024; off <<= 1) {
        int v = (t >= off) ? scan[t - off] : 0;
        __syncthreads();
        scan[t] += v;
        __syncthreads();
    }
    total = scan[1023];
    if (keep) g_rmv[b * OUTL + scan[t] - 1] = t;
    for (int r = t; r < OUTL; r += 1024)
        if (r >= total) g_rmv[b * OUTL + r] = -1;
    __syncthreads();
    if (t < n) g_rmv[b * OUTL + total + t] = g_vv[b * KTOP + t];
}

__global__ void copy_lang(const float* __restrict__ lang, float* __restrict__ out) {
    int r = blockIdx.x, b = blockIdx.y, t = threadIdx.x;
    int s = g_rml[b * OUTL + r];
    if (s == -2) return;  // merged row, written by combine
    float4* dst = (float4*)(out + ((long)b * OUTL + r) * Dn);
    if (s >= 0) {
        const float4* src = (const float4*)(lang + ((long)b * Ln + s) * Dn);
        for (int i = t; i < Dn / 4; i += 256) dst[i] = src[i];
    } else {
        float4 z = make_float4(0.f, 0.f, 0.f, 0.f);
        for (int i = t; i < Dn / 4; i += 256) dst[i] = z;
    }
}

__global__ void copy_vis(const float* __restrict__ vis, float* __restrict__ out) {
    int r = blockIdx.x, b = blockIdx.y, t = threadIdx.x;
    int s = g_rmv[b * OUTL + r];
    float4* dst = (float4*)(out + ((long)b * OUTL + r) * DVn);
    if (s >= 0) {
        const float4* src = (const float4*)(vis + ((long)b * Vn + s) * DVn);
        for (int i = t; i < DVn / 4; i += 256) dst[i] = src[i];
    } else {
        float4 z = make_float4(0.f, 0.f, 0.f, 0.f);
        for (int i = t; i < DVn / 4; i += 256) dst[i] = z;
    }
}

// x row = concat(lang[b, vl], visproj[b, vv])
__global__ void gather_x(const float* __restrict__ lang) {
    int i = blockIdx.x, b = blockIdx.y, t = threadIdx.x;
    float* x = g_x + ((long)b * KTOP + i) * XD;
    if (i < g_n[b]) {
        const float4* lt = (const float4*)(lang + ((long)b * Ln + g_vl[b * KTOP + i]) * Dn);
        const float4* vt = (const float4*)(g_visproj + ((long)b * Vn + g_vv[b * KTOP + i]) * Dn);
        float4* x0 = (float4*)x;
        float4* x1 = (float4*)(x + Dn);
        for (int d = t; d < Dn / 4; d += 256) { x0[d] = lt[d]; x1[d] = vt[d]; }
    } else {
        float4 z = make_float4(0.f, 0.f, 0.f, 0.f);
        float4* x0 = (float4*)x;
        for (int d = t; d < XD / 4; d += 256) x0[d] = z;
    }
}

// h = relu(x @ W_m1^T + b_m1)   (tolerance-loose: plain accumulation)
__global__ __launch_bounds__(256) void gemm_mlp(const float* __restrict__ Wm1,
                                                const float* __restrict__ bm1) {
    const float* A = g_x + (long)blockIdx.y * 128 * XD;
    const float* B = Wm1 + (long)blockIdx.x * 128 * XD;
    unsigned long long acc[8][4];
    #pragma unroll
    for (int i = 0; i < 8; i++)
        #pragma unroll
        for (int p = 0; p < 4; p++) acc[i][p] = 0ULL;
    sgemm_128_plain(A, B, XD, acc);
    int tx = (threadIdx.x & 15) << 3;
    int ty = (threadIdx.x >> 4) << 3;
    int m0 = blockIdx.y * 128 + ty;
    int n0 = blockIdx.x * 128 + tx;
    #pragma unroll
    for (int i = 0; i < 8; i++)
        #pragma unroll
        for (int p = 0; p < 4; p++) {
            float2 v = unpack_f32x2(acc[i][p]);
            int j = n0 + 2 * p;
            g_h[(long)(m0 + i) * HD + j]     = fmaxf(v.x + bm1[j], 0.f);
            g_h[(long)(m0 + i) * HD + j + 1] = fmaxf(v.y + bm1[j + 1], 0.f);
        }
}

// logits = h @ W_m2^T + b_m2 ; softmax ; merged = w0*lt + w1*vt
__global__ void combine(const float* __restrict__ lang, const float* __restrict__ Wm2,
                        const float* __restrict__ bm2, float* __restrict__ out) {
    int i = blockIdx.x, b = blockIdx.y, t = threadIdx.x;
    if (i >= g_n[b]) return;
    const float* h = g_h + ((long)b * KTOP + i) * HD;
    float s0 = 0.f, s1 = 0.f;
    for (int k = t; k < HD; k += 256) {
        float hv = h[k];
        s0 += hv * Wm2[k];
        s1 += hv * Wm2[HD + k];
    }
    __shared__ float r0[256], r1[256];
    r0[t] = s0; r1[t] = s1; __syncthreads();
    for (int off = 128; off > 0; off >>= 1) {
        if (t < off) { r0[t] += r0[t + off]; r1[t] += r1[t + off]; }
        __syncthreads();
    }
    float l0 = r0[0] + bm2[0], l1 = r1[0] + bm2[1];
    float mx = fmaxf(l0, l1);
    float e0 = expf(l0 - mx), e1 = expf(l1 - mx);
    float w0 = __fdiv_rn(e0, e0 + e1), w1 = __fdiv_rn(e1, e0 + e1);
    int row = g_nkl[b] + i;
    float* dst = out + ((long)b * OUTL + row) * Dn;
    const float* lt = lang + ((long)b * Ln + g_vl[b * KTOP + i]) * Dn;
    const float* vt = g_visproj + ((long)b * Vn + g_vv[b * KTOP + i]) * Dn;
    for (int d = t; d < Dn; d += 256) dst[d] = w0 * lt[d] + w1 * vt[d];
}

// ---------------- host launch ----------------
extern "C" void kernel_launch(void* const* d_in, const int* in_sizes, int n_in,
                              void* d_out, int out_size) {
    const float* lang = (const float*)d_in[0];
    const float* vis  = (const float*)d_in[1];
    const float* Wv2l = (const float*)d_in[2];
    const float* bv2l = (const float*)d_in[3];
    const float* Wm1  = (const float*)d_in[4];
    const float* bm1  = (const float*)d_in[5];
    const float* Wm2  = (const float*)d_in[6];
    const float* bm2  = (const float*)d_in[7];

    float* out      = (float*)d_out;
    float* out_lang = out;                                   // [8,1536,2048]
    float* out_vis  = out + (long)Bn * OUTL * Dn;            // [8,1536,1024]
    float* out_sim  = out_vis + (long)Bn * OUTL * DVn;       // [8,1024,1024]

    float* lhat;  cudaGetSymbolAddress((void**)&lhat, g_lhat);
    float* vhat;  cudaGetSymbolAddress((void**)&vhat, g_vhat);
    float* vproj; cudaGetSymbolAddress((void**)&vproj, g_visproj);

    reset_counters<<<1, 32>>>();
    normalize_rows<<<Bn * Ln, 256>>>(lang, lhat);
    gemm_visproj<<<dim3(Dn / 128, Vn / 128, Bn), 256>>>(vis, Wv2l, bv2l);
    normalize_rows<<<Bn * Vn, 256>>>(vproj, vhat);
    gemm_sim<<<dim3(Vn / 128, Ln / 128, Bn), 256>>>(out_sim);
    sort_cand<<<Bn, 1024>>>();
    select_pairs<<<Bn, KTOP>>>();
    build_rowmap<<<Bn, 1024>>>();
    copy_lang<<<dim3(OUTL, Bn), 256>>>(lang, out_lang);
    copy_vis<<<dim3(OUTL, Bn), 256>>>(vis, out_vis);
    gather_x<<<dim3(KTOP, Bn), 256>>>(lang);
    gemm_mlp<<<dim3(HD / 128, (Bn * KTOP) / 128, 1), 256>>>(Wm1, bm1);
    combine<<<dim3(KTOP, Bn), 256>>>(lang, Wm2, bm2, out_lang);
}